// round 8
// baseline (speedup 1.0000x reference)
#include <cuda_runtime.h>
#include <cstdint>

#define NW 14
#define NSTATE (1 << NW)        // 16384 amplitudes
#define NLAYERS 6               // (DEPTH+1) * SEL_LAYERS
#define NTHREADS 1024
#define NWARPS (NTHREADS / 32)
#define NPARAMS (2 * NW * 3)    // 84

// ---------------------------------------------------------------------------
// Compile-time GF(2) algebra: lazy CNOT permutation tracking.
// Storage invariant: psi[x] = a[T * x] (T invertible 14x14 over GF(2)).
// Rot on wire w pairs physical (j, j^v), v = col_w(T); role parity =
// <row_w(Tinv), j>, and <row_w(Tinv), col_w'(T)> = delta -> lane-combo terms
// drop out of parities.  Linear swizzle sw(j)=j^(j>>4)^(j>>9) folded in.
// Layer = 2 warp-private super-sweeps:
//   SS_A: wires 0-7  -> 256-amp blocks, 2 blocks/warp, groups {0-3},{4-7}
//   SS_B: wires 8-13 ->  64-amp blocks, 8 blocks/warp, groups {8-10},{11-13}
// Within a super-sweep only __syncwarp() is needed between the two groups.
// ---------------------------------------------------------------------------

struct LayerTab {
    uint16_t v[NW];      // T columns for this layer
    uint16_t umask[NW];  // Tinv rows  (role-parity masks)
    uint8_t  uidx[NW];   // gate matrix index: (L&1)*NW + w
    int      pivA[8];    // sorted pivots of span{v0..v7}
    int      pivB[6];    // sorted pivots of span{v8..v13}
};
struct AllTabs {
    LayerTab lay[NLAYERS];
    uint16_t zu[NW];     // final Tinv rows -> measurement sign masks
};

__host__ __device__ constexpr unsigned swz(unsigned j) {
    return j ^ (j >> 4) ^ (j >> 9);
}

__host__ __device__ constexpr AllTabs build_all() {
    AllTabs t{};
    uint16_t Tcol[NW]  = {};
    uint16_t TiRow[NW] = {};
    for (int i = 0; i < NW; i++) { Tcol[i] = (uint16_t)(1u << i); TiRow[i] = (uint16_t)(1u << i); }

    for (int L = 0; L < NLAYERS; L++) {
        LayerTab& lt = t.lay[L];
        for (int w = 0; w < NW; w++) {
            lt.v[w]     = Tcol[w];
            lt.umask[w] = TiRow[w];
            lt.uidx[w]  = (uint8_t)((L & 1) * NW + w);
        }
        // pivots of span{v0..v7}
        {
            uint16_t red[8] = {};
            for (int i = 0; i < 8; i++) red[i] = Tcol[i];
            int piv[8] = {};
            for (int i = 0; i < 8; i++) {
                int p = 0; while (((red[i] >> p) & 1) == 0) p++;
                piv[i] = p;
                for (int j = 0; j < 8; j++)
                    if (j != i && ((red[j] >> p) & 1)) red[j] = (uint16_t)(red[j] ^ red[i]);
            }
            for (int a = 0; a < 8; a++)
                for (int b = a + 1; b < 8; b++)
                    if (piv[b] < piv[a]) { int tmp = piv[a]; piv[a] = piv[b]; piv[b] = tmp; }
            for (int i = 0; i < 8; i++) lt.pivA[i] = piv[i];
        }
        // pivots of span{v8..v13}
        {
            uint16_t red[6] = {};
            for (int i = 0; i < 6; i++) red[i] = Tcol[8 + i];
            int piv[6] = {};
            for (int i = 0; i < 6; i++) {
                int p = 0; while (((red[i] >> p) & 1) == 0) p++;
                piv[i] = p;
                for (int j = 0; j < 6; j++)
                    if (j != i && ((red[j] >> p) & 1)) red[j] = (uint16_t)(red[j] ^ red[i]);
            }
            for (int a = 0; a < 6; a++)
                for (int b = a + 1; b < 6; b++)
                    if (piv[b] < piv[a]) { int tmp = piv[a]; piv[a] = piv[b]; piv[b] = tmp; }
            for (int i = 0; i < 6; i++) lt.pivB[i] = piv[i];
        }
        // CNOT ring layer, range r = (L%2)+1:  T' = T*Q,  Tinv' = Qinv*Tinv
        int r = (L & 1) + 1;
        uint16_t Qrow[NW]  = {};
        uint16_t QiRow[NW] = {};
        for (int i = 0; i < NW; i++) { Qrow[i] = (uint16_t)(1u << i); QiRow[i] = (uint16_t)(1u << i); }
        for (int w = NW - 1; w >= 0; w--) Qrow[(w + r) % NW]  = (uint16_t)(Qrow[(w + r) % NW]  ^ Qrow[w]);
        for (int w = 0; w < NW; w++)      QiRow[(w + r) % NW] = (uint16_t)(QiRow[(w + r) % NW] ^ QiRow[w]);
        uint16_t nT[NW]  = {};
        uint16_t nTi[NW] = {};
        for (int w = 0; w < NW; w++) {
            uint16_t c = 0;
            for (int i = 0; i < NW; i++) if ((Qrow[i] >> w) & 1) c = (uint16_t)(c ^ Tcol[i]);
            nT[w] = c;
        }
        for (int i = 0; i < NW; i++) {
            uint16_t rr = 0;
            for (int k = 0; k < NW; k++) if ((QiRow[i] >> k) & 1) rr = (uint16_t)(rr ^ TiRow[k]);
            nTi[i] = rr;
        }
        for (int i = 0; i < NW; i++) { Tcol[i] = nT[i]; TiRow[i] = nTi[i]; }
    }
    for (int i = 0; i < NW; i++) t.zu[i] = TiRow[i];
    return t;
}

struct O16 { uint16_t o[16]; };
__host__ __device__ constexpr O16 make_offs(int L, int w0, int G) {
    AllTabs t = build_all();
    O16 r{};
    for (int m = 0; m < (1 << G); m++) {
        uint16_t x = 0;
        for (int i = 0; i < G; i++) if ((m >> i) & 1) x = (uint16_t)(x ^ t.lay[L].v[w0 + i]);
        r.o[m] = (uint16_t)swz(x);
    }
    return r;
}

// ---------------------------------------------------------------------------
// Packed f32x2 complex helpers. Amplitude packed as u64: lo=re, hi=im.
// ---------------------------------------------------------------------------
typedef unsigned long long u64;

__device__ __forceinline__ u64 pk(float lo, float hi) {
    u64 r; asm("mov.b64 %0, {%1,%2};" : "=l"(r) : "f"(lo), "f"(hi)); return r;
}
__device__ __forceinline__ u64 sw64(u64 a) {
    unsigned lo, hi;
    asm("mov.b64 {%0,%1}, %2;" : "=r"(lo), "=r"(hi) : "l"(a));
    u64 r; asm("mov.b64 %0, {%1,%2};" : "=l"(r) : "r"(hi), "r"(lo)); return r;
}
__device__ __forceinline__ u64 fma2_(u64 a, u64 b, u64 c) {
    u64 d; asm("fma.rn.f32x2 %0, %1, %2, %3;" : "=l"(d) : "l"(a), "l"(b), "l"(c)); return d;
}
__device__ __forceinline__ u64 mul2_(u64 a, u64 b) {
    u64 d; asm("mul.rn.f32x2 %0, %1, %2;" : "=l"(d) : "l"(a), "l"(b)); return d;
}

#define SGNC 0x8000000080000000ULL

// Apply G commuting Rot gates (wires W0..W0+G-1 of layer L) to a register
// coset a[2^G].  SU(2): role-swap = sign flips only.
template <int L, int W0, int G>
__device__ __forceinline__ void gates_on_regs(u64* a, unsigned base,
                                              const u64* __restrict__ Us) {
    constexpr LayerTab lt = build_all().lay[L];
#pragma unroll
    for (int i = 0; i < G; i++) {
        const u64* Ub = Us + (int)lt.uidx[W0 + i] * 4;   // broadcast LDS
        u64 bb   = (u64)(__popc(base & (unsigned)lt.umask[W0 + i]) & 1u);
        u64 mask = (0ULL - bb) & SGNC;
        u64 A  = Ub[0];
        u64 B  = Ub[1] ^ mask;                           // w00_pm
        u64 Bn = B ^ SGNC;                               // w11_pm
        u64 C  = Ub[2] ^ mask;                           // w01_rr
        u64 Cn = C ^ SGNC;                               // w10_rr
        u64 D  = Ub[3];                                  // w01_pm == w10_pm
#pragma unroll
        for (int m = 0; m < (1 << G); m++) {
            if (m & (1 << i)) continue;
            u64 a0 = a[m], a1 = a[m | (1 << i)];
            u64 a0s = sw64(a0), a1s = sw64(a1);
            a[m]            = fma2_(A, a0, fma2_(B,  a0s, fma2_(C,  a1, mul2_(D, a1s))));
            a[m | (1 << i)] = fma2_(A, a1, fma2_(Bn, a1s, fma2_(Cn, a0, mul2_(D, a0s))));
        }
    }
}

// Super-sweep A: wires 0-7.  Warp owns 2 256-amp blocks; only __syncwarp
// between the two 4-gate groups.
template <int L>
__device__ __forceinline__ void ss_A(u64* __restrict__ st, const u64* __restrict__ Us) {
    constexpr LayerTab lt = build_all().lay[L];
    constexpr O16 o0 = make_offs(L, 0, 4);
    constexpr O16 o1 = make_offs(L, 4, 4);

    const unsigned lane = threadIdx.x & 31u, wp = threadIdx.x >> 5;
    unsigned rep = wp * 2 + (lane >> 4);                 // block id in [0,64)
#pragma unroll
    for (int i = 0; i < 8; i++) {                        // insert zeros at pivA
        unsigned lm = (1u << lt.pivA[i]) - 1u;
        rep = ((rep & ~lm) << 1) | (rep & lm);
    }
    const unsigned l4 = lane & 15u;
    unsigned lc0 = 0, lc1 = 0;
#pragma unroll
    for (int i = 0; i < 4; i++) {
        if (l4 & (1u << i)) { lc0 ^= lt.v[4 + i]; lc1 ^= lt.v[i]; }
    }
    {   // group: wires 0-3; lane-combo spans v4..v7 (orthogonal to umask 0-3)
        unsigned base = rep ^ lc0, sb = swz(base);
        u64 a[16];
#pragma unroll
        for (int m = 0; m < 16; m++) a[m] = st[sb ^ (unsigned)o0.o[m]];
        gates_on_regs<L, 0, 4>(a, base, Us);
#pragma unroll
        for (int m = 0; m < 16; m++) st[sb ^ (unsigned)o0.o[m]] = a[m];
    }
    __syncwarp(0xffffffffu);
    {   // group: wires 4-7
        unsigned base = rep ^ lc1, sb = swz(base);
        u64 a[16];
#pragma unroll
        for (int m = 0; m < 16; m++) a[m] = st[sb ^ (unsigned)o1.o[m]];
        gates_on_regs<L, 4, 4>(a, base, Us);
#pragma unroll
        for (int m = 0; m < 16; m++) st[sb ^ (unsigned)o1.o[m]] = a[m];
    }
}

// Super-sweep B: wires 8-13.  Warp owns 8 64-amp blocks (2 iterations/thread,
// independent -> ILP); only __syncwarp between the two 3-gate groups.
template <int L>
__device__ __forceinline__ void ss_B(u64* __restrict__ st, const u64* __restrict__ Us) {
    constexpr LayerTab lt = build_all().lay[L];
    constexpr O16 o2 = make_offs(L, 8, 3);
    constexpr O16 o3 = make_offs(L, 11, 3);

    const unsigned lane = threadIdx.x & 31u, wp = threadIdx.x >> 5;
    const unsigned l3 = lane & 7u;
    unsigned lc2 = 0, lc3 = 0;
#pragma unroll
    for (int i = 0; i < 3; i++) {
        if (l3 & (1u << i)) { lc2 ^= lt.v[11 + i]; lc3 ^= lt.v[8 + i]; }
    }
    unsigned rep[2];
#pragma unroll
    for (int it = 0; it < 2; it++) {
        unsigned r = wp * 8 + ((lane >> 3) & 3u) + (unsigned)(it << 2);  // block in [0,256)
#pragma unroll
        for (int i = 0; i < 6; i++) {                    // insert zeros at pivB
            unsigned lm = (1u << lt.pivB[i]) - 1u;
            r = ((r & ~lm) << 1) | (r & lm);
        }
        rep[it] = r;
    }
#pragma unroll
    for (int it = 0; it < 2; it++) {                     // wires 8-10
        unsigned base = rep[it] ^ lc2, sb = swz(base);
        u64 a[8];
#pragma unroll
        for (int m = 0; m < 8; m++) a[m] = st[sb ^ (unsigned)o2.o[m]];
        gates_on_regs<L, 8, 3>(a, base, Us);
#pragma unroll
        for (int m = 0; m < 8; m++) st[sb ^ (unsigned)o2.o[m]] = a[m];
    }
    __syncwarp(0xffffffffu);
#pragma unroll
    for (int it = 0; it < 2; it++) {                     // wires 11-13
        unsigned base = rep[it] ^ lc3, sb = swz(base);
        u64 a[8];
#pragma unroll
        for (int m = 0; m < 8; m++) a[m] = st[sb ^ (unsigned)o3.o[m]];
        gates_on_regs<L, 11, 3>(a, base, Us);
#pragma unroll
        for (int m = 0; m < 8; m++) st[sb ^ (unsigned)o3.o[m]] = a[m];
    }
}

__global__ void __launch_bounds__(NTHREADS, 1)
qsim_kernel(const float* __restrict__ state_batch,
            const float* __restrict__ params,
            const float* __restrict__ head_w,
            const float* __restrict__ head_b,
            float* __restrict__ out) {
    extern __shared__ u64 st[];                    // 16384 x 8B = 128 KB
    __shared__ u64   Usm[2 * NW * 4];              // 28 gates x {u_rr,u_pm,v_rr,v_pm}
    __shared__ float redsm[NWARPS * NW];

    const int b   = blockIdx.x;
    const int tid = threadIdx.x;

    // zero state
#pragma unroll
    for (int i = tid; i < NSTATE; i += NTHREADS) st[i] = 0ULL;

    // 28 distinct Rot matrices (weights shared across the 3 blocks).
    // Rot = [[u, v], [-conj(v), conj(u)]]: u = e^{-i(phi+om)/2} cos(th/2),
    // v = -e^{+i(phi-om)/2} sin(th/2).
    if (tid < 2 * NW) {
        const float* p = params + (size_t)b * NPARAMS + tid * 3;
        float phi = p[0], th = p[1], om = p[2];
        float s, c;  sincosf(0.5f * th, &s, &c);
        float sa, ca; sincosf(0.5f * (phi + om), &sa, &ca);
        float sb, cb; sincosf(0.5f * (phi - om), &sb, &cb);
        float ur =  ca * c, ui = -sa * c;
        float vr = -cb * s, vi = -sb * s;
        u64* U = &Usm[tid * 4];
        U[0] = pk( ur, ur);     // u_rr
        U[1] = pk(-ui, ui);     // u_pm
        U[2] = pk( vr, vr);     // v_rr
        U[3] = pk(-vi, vi);     // v_pm
    }
    __syncthreads();

    // AngleEmbedding: RX(0 or pi) -> basis state (global phase irrelevant)
    if (tid == 0) {
        unsigned j0 = 0;
        const float* sb_ = state_batch + (size_t)b * (NSTATE * 2);
        for (int w = 0; w < NW; w++) if (sb_[w] < 0.f) j0 |= (1u << w);
        st[swz(j0)] = pk(1.f, 0.f);
    }
    __syncthreads();

    // 6 layers, 2 full barriers each (CNOT layers free, folded into tables)
    ss_A<0>(st, Usm); __syncthreads(); ss_B<0>(st, Usm); __syncthreads();
    ss_A<1>(st, Usm); __syncthreads(); ss_B<1>(st, Usm); __syncthreads();
    ss_A<2>(st, Usm); __syncthreads(); ss_B<2>(st, Usm); __syncthreads();
    ss_A<3>(st, Usm); __syncthreads(); ss_B<3>(st, Usm); __syncthreads();
    ss_A<4>(st, Usm); __syncthreads(); ss_B<4>(st, Usm); __syncthreads();
    ss_A<5>(st, Usm); __syncthreads(); ss_B<5>(st, Usm); __syncthreads();

    // <Z_w> via final Tinv sign masks, then linear head
    constexpr AllTabs tt = build_all();
    float acc[NW];
#pragma unroll
    for (int w = 0; w < NW; w++) acc[w] = 0.f;
#pragma unroll
    for (int kk = 0; kk < NSTATE / NTHREADS; kk++) {
        unsigned j = (unsigned)(tid + kk * NTHREADS);
        u64 av = st[swz(j)];
        float ax = __uint_as_float((unsigned)av);
        float ay = __uint_as_float((unsigned)(av >> 32));
        float pv = ax * ax + ay * ay;
        unsigned pb = __float_as_uint(pv);
#pragma unroll
        for (int w = 0; w < NW; w++) {
            unsigned s = (__popc(j & (unsigned)tt.zu[w]) & 1u) << 31;
            acc[w] += __uint_as_float(pb ^ s);
        }
    }
#pragma unroll
    for (int w = 0; w < NW; w++) {
#pragma unroll
        for (int o = 16; o > 0; o >>= 1) acc[w] += __shfl_xor_sync(0xffffffffu, acc[w], o);
    }
    const int lane = tid & 31, warp = tid >> 5;
    if (lane == 0) {
#pragma unroll
        for (int w = 0; w < NW; w++) redsm[warp * NW + w] = acc[w];
    }
    __syncthreads();
    if (warp == 0 && lane < NW) {
        float z = 0.f;
#pragma unroll
        for (int k = 0; k < NWARPS; k++) z += redsm[k * NW + lane];
        redsm[lane] = z * head_w[lane];
    }
    __syncthreads();
    if (tid == 0) {
        float r_ = head_b[0];
#pragma unroll
        for (int w = 0; w < NW; w++) r_ += redsm[w];
        out[b] = r_;
    }
}

extern "C" void kernel_launch(void* const* d_in, const int* in_sizes, int n_in,
                              void* d_out, int out_size) {
    const float* state_batch = (const float*)d_in[0];
    const float* params      = (const float*)d_in[1];
    const float* head_w      = (const float*)d_in[2];
    const float* head_b      = (const float*)d_in[3];
    float* out = (float*)d_out;

    int B = in_sizes[0] / (NSTATE * 2);   // 512
    cudaFuncSetAttribute(qsim_kernel, cudaFuncAttributeMaxDynamicSharedMemorySize,
                         NSTATE * (int)sizeof(u64));
    qsim_kernel<<<B, NTHREADS, NSTATE * sizeof(u64)>>>(state_batch, params, head_w, head_b, out);
}

// round 9
// speedup vs baseline: 1.2499x; 1.2499x over previous
#include <cuda_runtime.h>
#include <cstdint>

#define NW 14
#define NSTATE (1 << NW)        // 16384 amplitudes
#define NLAYERS 6               // (DEPTH+1) * SEL_LAYERS
#define NTHREADS 1024
#define NWARPS (NTHREADS / 32)
#define NPARAMS (2 * NW * 3)    // 84

// ---------------------------------------------------------------------------
// Compile-time GF(2) algebra: lazy CNOT permutation tracking.
// psi[x] = a[T*x]; Rot on wire w pairs (j, j^v), v = col_w(T); role parity =
// <row_w(Tinv), j>.  Storage swizzle sw(j)=j^(j>>4)^(j>>9) (linear).
// NEW: per-sweep coset representatives chosen from a constexpr complement
// basis whose 4 lane-bit vectors have GF(2)-independent bank-pair images
// low4(sw(w_i)) -> every LDS.64/STS.64 is exactly 2-phase (HW minimum).
// ---------------------------------------------------------------------------

struct LayerTab {
    uint16_t v[NW];      // T columns for this layer
    uint16_t umask[NW];  // Tinv rows (role-parity masks)
    uint8_t  uidx[NW];   // gate matrix index: (L&1)*NW + w
};
struct AllTabs {
    LayerTab lay[NLAYERS];
    uint16_t zu[NW];     // final Tinv rows -> measurement sign masks
};

__host__ __device__ constexpr unsigned swz(unsigned j) {
    return j ^ (j >> 4) ^ (j >> 9);
}

__host__ __device__ constexpr AllTabs build_all() {
    AllTabs t{};
    uint16_t Tcol[NW]  = {};
    uint16_t TiRow[NW] = {};
    for (int i = 0; i < NW; i++) { Tcol[i] = (uint16_t)(1u << i); TiRow[i] = (uint16_t)(1u << i); }

    for (int L = 0; L < NLAYERS; L++) {
        LayerTab& lt = t.lay[L];
        for (int w = 0; w < NW; w++) {
            lt.v[w]     = Tcol[w];
            lt.umask[w] = TiRow[w];
            lt.uidx[w]  = (uint8_t)((L & 1) * NW + w);
        }
        // CNOT ring layer, range r = (L%2)+1:  T' = T*Q,  Tinv' = Qinv*Tinv
        int r = (L & 1) + 1;
        uint16_t Qrow[NW]  = {};
        uint16_t QiRow[NW] = {};
        for (int i = 0; i < NW; i++) { Qrow[i] = (uint16_t)(1u << i); QiRow[i] = (uint16_t)(1u << i); }
        for (int w = NW - 1; w >= 0; w--) Qrow[(w + r) % NW]  = (uint16_t)(Qrow[(w + r) % NW]  ^ Qrow[w]);
        for (int w = 0; w < NW; w++)      QiRow[(w + r) % NW] = (uint16_t)(QiRow[(w + r) % NW] ^ QiRow[w]);
        uint16_t nT[NW]  = {};
        uint16_t nTi[NW] = {};
        for (int w = 0; w < NW; w++) {
            uint16_t c = 0;
            for (int i = 0; i < NW; i++) if ((Qrow[i] >> w) & 1) c = (uint16_t)(c ^ Tcol[i]);
            nT[w] = c;
        }
        for (int i = 0; i < NW; i++) {
            uint16_t rr = 0;
            for (int k = 0; k < NW; k++) if ((QiRow[i] >> k) & 1) rr = (uint16_t)(rr ^ TiRow[k]);
            nTi[i] = rr;
        }
        for (int i = 0; i < NW; i++) { Tcol[i] = nT[i]; TiRow[i] = nTi[i]; }
    }
    for (int i = 0; i < NW; i++) t.zu[i] = TiRow[i];
    return t;
}

// Candidate vectors for the complement-basis greedy: 14 units + 91 pairs.
__host__ __device__ constexpr uint16_t cand_vec(int idx) {
    if (idx < 14) return (uint16_t)(1u << idx);
    int k = idx - 14;
    for (int a = 0; a < 14; a++) {
        int cnt = 13 - a;
        if (k < cnt) return (uint16_t)((1u << a) | (1u << (a + 1 + k)));
        k -= cnt;
    }
    return 1;
}
#define NCAND (14 + 91)

struct SweepTab {
    uint16_t offs[16];   // pre-swizzled xor-offsets of coset members
    uint16_t umask[4];   // role-parity masks
    uint8_t  uidx[4];    // gate matrix indices
    uint16_t w[11];      // complement basis; w[i] multiplies bit i of c
};

__host__ __device__ constexpr SweepTab make_sweep(int L, int g) {
    AllTabs t = build_all();
    const int GS[4] = {4, 4, 3, 3};
    const int W0[4] = {0, 4, 8, 11};
    const int G = GS[g], w0 = W0[g];
    SweepTab s{};
    for (int i = 0; i < G; i++) { s.umask[i] = t.lay[L].umask[w0 + i]; s.uidx[i] = t.lay[L].uidx[w0 + i]; }
    for (int i = G; i < 4; i++) { s.umask[i] = 0; s.uidx[i] = 0; }
    for (int m = 0; m < (1 << G); m++) {
        uint16_t x = 0;
        for (int i = 0; i < G; i++) if ((m >> i) & 1) x = (uint16_t)(x ^ t.lay[L].v[w0 + i]);
        s.offs[m] = (uint16_t)swz(x);
    }
    for (int m = (1 << G); m < 16; m++) s.offs[m] = 0;

    // Row-echelon span tracker, seeded with the gate span V.
    uint16_t ech[14] = {};
    for (int i = 0; i < G; i++) {
        uint16_t x = t.lay[L].v[w0 + i];
        for (int b = 13; b >= 0; b--) if (((x >> b) & 1) && ech[b]) x = (uint16_t)(x ^ ech[b]);
        if (x) { int b = 13; while (!((x >> b) & 1)) b--; ech[b] = x; }
    }
    uint16_t bech[4] = {};       // bank-pair image echelon (4-bit)
    const int need = 14 - G;
    for (int i = 0; i < need; i++) {
        uint16_t pick = 0; bool found = false; bool bankok = false;
        for (int ci = 0; ci < NCAND && !found; ci++) {   // pass 1: span + bank rank
            uint16_t x0 = cand_vec(ci), x = x0;
            for (int b = 13; b >= 0; b--) if (((x >> b) & 1) && ech[b]) x = (uint16_t)(x ^ ech[b]);
            if (!x) continue;
            if (i < 4) {
                uint16_t im = (uint16_t)(swz(x0) & 15u);
                for (int b = 3; b >= 0; b--) if (((im >> b) & 1) && bech[b]) im = (uint16_t)(im ^ bech[b]);
                if (!im) continue;
            }
            pick = x0; found = true; bankok = true;
        }
        for (int ci = 0; ci < NCAND && !found; ci++) {   // pass 2: span only (perf fallback)
            uint16_t x0 = cand_vec(ci), x = x0;
            for (int b = 13; b >= 0; b--) if (((x >> b) & 1) && ech[b]) x = (uint16_t)(x ^ ech[b]);
            if (!x) continue;
            pick = x0; found = true; bankok = false;
        }
        {   // insert into span echelon (guarantees independence -> correctness)
            uint16_t x = pick;
            for (int b = 13; b >= 0; b--) if (((x >> b) & 1) && ech[b]) x = (uint16_t)(x ^ ech[b]);
            if (x) { int b = 13; while (!((x >> b) & 1)) b--; ech[b] = x; }
        }
        if (i < 4 && bankok) {
            uint16_t im = (uint16_t)(swz(pick) & 15u);
            for (int b = 3; b >= 0; b--) if (((im >> b) & 1) && bech[b]) im = (uint16_t)(im ^ bech[b]);
            if (im) { int b = 3; while (!((im >> b) & 1)) b--; bech[b] = im; }
        }
        s.w[i] = pick;
    }
    for (int i = need; i < 11; i++) s.w[i] = 0;
    return s;
}

// ---------------------------------------------------------------------------
// Packed f32x2 complex helpers. Amplitude packed as u64: lo=re, hi=im.
// ---------------------------------------------------------------------------
typedef unsigned long long u64;

__device__ __forceinline__ u64 pk(float lo, float hi) {
    u64 r; asm("mov.b64 %0, {%1,%2};" : "=l"(r) : "f"(lo), "f"(hi)); return r;
}
__device__ __forceinline__ u64 sw64(u64 a) {
    unsigned lo, hi;
    asm("mov.b64 {%0,%1}, %2;" : "=r"(lo), "=r"(hi) : "l"(a));
    u64 r; asm("mov.b64 %0, {%1,%2};" : "=l"(r) : "r"(hi), "r"(lo)); return r;
}
__device__ __forceinline__ u64 fma2_(u64 a, u64 b, u64 c) {
    u64 d; asm("fma.rn.f32x2 %0, %1, %2, %3;" : "=l"(d) : "l"(a), "l"(b), "l"(c)); return d;
}
__device__ __forceinline__ u64 mul2_(u64 a, u64 b) {
    u64 d; asm("mul.rn.f32x2 %0, %1, %2;" : "=l"(d) : "l"(a), "l"(b)); return d;
}

#define SGNC 0x8000000080000000ULL

// ---------------------------------------------------------------------------
// Fused multi-gate sweep with bank-optimal coset enumeration.
// ---------------------------------------------------------------------------
template <int L, int g, int G>
__device__ __forceinline__ void sweep(u64* __restrict__ st,
                                      const u64* __restrict__ Us) {
    constexpr SweepTab tb = make_sweep(L, g);
    constexpr int NB = 14 - G;
    constexpr int NITER = (NSTATE >> G) / NTHREADS;

#pragma unroll
    for (int kk = 0; kk < NITER; kk++) {
        unsigned c = threadIdx.x + kk * NTHREADS;
        unsigned rep = 0;
#pragma unroll
        for (int i = 0; i < NB; i++)
            rep ^= (c & (1u << i)) ? (unsigned)tb.w[i] : 0u;
        unsigned sj = swz(rep);
        u64 a[1 << G];
#pragma unroll
        for (int m = 0; m < (1 << G); m++) a[m] = st[sj ^ (unsigned)tb.offs[m]];
#pragma unroll
        for (int i = 0; i < G; i++) {
            const u64* Ub = Us + (int)tb.uidx[i] * 4;    // broadcast LDS
            u64 bb   = (u64)(__popc(rep & (unsigned)tb.umask[i]) & 1u);
            u64 mask = (0ULL - bb) & SGNC;
            u64 A  = Ub[0];
            u64 B  = Ub[1] ^ mask;                       // w00_pm
            u64 Bn = B ^ SGNC;                           // w11_pm
            u64 C  = Ub[2] ^ mask;                       // w01_rr
            u64 Cn = C ^ SGNC;                           // w10_rr
            u64 D  = Ub[3];                              // w01_pm == w10_pm
#pragma unroll
            for (int m = 0; m < (1 << G); m++) {
                if (m & (1 << i)) continue;
                u64 a0 = a[m], a1 = a[m | (1 << i)];
                u64 a0s = sw64(a0), a1s = sw64(a1);
                a[m]            = fma2_(A, a0, fma2_(B,  a0s, fma2_(C,  a1, mul2_(D, a1s))));
                a[m | (1 << i)] = fma2_(A, a1, fma2_(Bn, a1s, fma2_(Cn, a0, mul2_(D, a0s))));
            }
        }
#pragma unroll
        for (int m = 0; m < (1 << G); m++) st[sj ^ (unsigned)tb.offs[m]] = a[m];
    }
}

template <int L>
__device__ __forceinline__ void layer(u64* __restrict__ st, const u64* __restrict__ Us) {
    sweep<L, 0, 4>(st, Us); __syncthreads();
    sweep<L, 1, 4>(st, Us); __syncthreads();
    sweep<L, 2, 3>(st, Us); __syncthreads();
    sweep<L, 3, 3>(st, Us); __syncthreads();
}

__global__ void __launch_bounds__(NTHREADS, 1)
qsim_kernel(const float* __restrict__ state_batch,
            const float* __restrict__ params,
            const float* __restrict__ head_w,
            const float* __restrict__ head_b,
            float* __restrict__ out) {
    extern __shared__ u64 st[];                    // 16384 x 8B = 128 KB
    __shared__ u64   Usm[2 * NW * 4];              // 28 gates x {u_rr,u_pm,v_rr,v_pm}
    __shared__ float redsm[NWARPS * NW];

    const int b   = blockIdx.x;
    const int tid = threadIdx.x;

    // zero state
#pragma unroll
    for (int i = tid; i < NSTATE; i += NTHREADS) st[i] = 0ULL;

    // 28 distinct Rot matrices (weights shared across the 3 blocks).
    // Rot = [[u, v], [-conj(v), conj(u)]]: u = e^{-i(phi+om)/2} cos(th/2),
    // v = -e^{+i(phi-om)/2} sin(th/2).
    if (tid < 2 * NW) {
        const float* p = params + (size_t)b * NPARAMS + tid * 3;
        float phi = p[0], th = p[1], om = p[2];
        float s, c;  sincosf(0.5f * th, &s, &c);
        float sa, ca; sincosf(0.5f * (phi + om), &sa, &ca);
        float sb, cb; sincosf(0.5f * (phi - om), &sb, &cb);
        float ur =  ca * c, ui = -sa * c;
        float vr = -cb * s, vi = -sb * s;
        u64* U = &Usm[tid * 4];
        U[0] = pk( ur, ur);     // u_rr
        U[1] = pk(-ui, ui);     // u_pm
        U[2] = pk( vr, vr);     // v_rr
        U[3] = pk(-vi, vi);     // v_pm
    }
    __syncthreads();

    // AngleEmbedding: RX(0 or pi) -> basis state (global phase irrelevant)
    if (tid == 0) {
        unsigned j0 = 0;
        const float* sb_ = state_batch + (size_t)b * (NSTATE * 2);
        for (int w = 0; w < NW; w++) if (sb_[w] < 0.f) j0 |= (1u << w);
        st[swz(j0)] = pk(1.f, 0.f);
    }
    __syncthreads();

    // 6 layers: 14 Rots each (fused 4+4+3+3); CNOT layers free (constexpr)
    layer<0>(st, Usm);
    layer<1>(st, Usm);
    layer<2>(st, Usm);
    layer<3>(st, Usm);
    layer<4>(st, Usm);
    layer<5>(st, Usm);

    // <Z_w> via final Tinv sign masks, then linear head
    constexpr AllTabs tt = build_all();
    float acc[NW];
#pragma unroll
    for (int w = 0; w < NW; w++) acc[w] = 0.f;
#pragma unroll
    for (int kk = 0; kk < NSTATE / NTHREADS; kk++) {
        unsigned j = (unsigned)(tid + kk * NTHREADS);
        u64 av = st[swz(j)];
        float ax = __uint_as_float((unsigned)av);
        float ay = __uint_as_float((unsigned)(av >> 32));
        float pv = ax * ax + ay * ay;
        unsigned pb = __float_as_uint(pv);
#pragma unroll
        for (int w = 0; w < NW; w++) {
            unsigned s = (__popc(j & (unsigned)tt.zu[w]) & 1u) << 31;
            acc[w] += __uint_as_float(pb ^ s);
        }
    }
#pragma unroll
    for (int w = 0; w < NW; w++) {
#pragma unroll
        for (int o = 16; o > 0; o >>= 1) acc[w] += __shfl_xor_sync(0xffffffffu, acc[w], o);
    }
    const int lane = tid & 31, warp = tid >> 5;
    if (lane == 0) {
#pragma unroll
        for (int w = 0; w < NW; w++) redsm[warp * NW + w] = acc[w];
    }
    __syncthreads();
    if (warp == 0 && lane < NW) {
        float z = 0.f;
#pragma unroll
        for (int k = 0; k < NWARPS; k++) z += redsm[k * NW + lane];
        redsm[lane] = z * head_w[lane];
    }
    __syncthreads();
    if (tid == 0) {
        float r_ = head_b[0];
#pragma unroll
        for (int w = 0; w < NW; w++) r_ += redsm[w];
        out[b] = r_;
    }
}

extern "C" void kernel_launch(void* const* d_in, const int* in_sizes, int n_in,
                              void* d_out, int out_size) {
    const float* state_batch = (const float*)d_in[0];
    const float* params      = (const float*)d_in[1];
    const float* head_w      = (const float*)d_in[2];
    const float* head_b      = (const float*)d_in[3];
    float* out = (float*)d_out;

    int B = in_sizes[0] / (NSTATE * 2);   // 512
    cudaFuncSetAttribute(qsim_kernel, cudaFuncAttributeMaxDynamicSharedMemorySize,
                         NSTATE * (int)sizeof(u64));
    qsim_kernel<<<B, NTHREADS, NSTATE * sizeof(u64)>>>(state_batch, params, head_w, head_b, out);
}

// round 10
// speedup vs baseline: 1.4786x; 1.1830x over previous
#include <cuda_runtime.h>
#include <cstdint>

#define NW 14
#define NSTATE (1 << NW)        // 16384 amplitudes
#define NLAYERS 6               // (DEPTH+1) * SEL_LAYERS
#define NTHREADS 512
#define NWARPS (NTHREADS / 32)
#define NPARAMS (2 * NW * 3)    // 84

// ---------------------------------------------------------------------------
// Compile-time GF(2) algebra: lazy CNOT permutation tracking.
// psi[x] = a[T*x]; Rot on wire w pairs (j, j^v), v = col_w(T); role parity =
// <row_w(Tinv), j>.  Storage swizzle sw(j)=j^(j>>4)^(j>>9) (linear).
// Layers regrouped as G=5+5+4 -> 18 sweeps total (was 24).
// Coset representatives come from a constexpr complement basis whose first 4
// lane-bit vectors have GF(2)-independent bank-pair images low4(sw(w_i)):
// every LDS.64/STS.64 is an exact 2:1 lane->bank-pair map (2-phase minimum).
// ---------------------------------------------------------------------------

struct LayerTab {
    uint16_t v[NW];      // T columns for this layer
    uint16_t umask[NW];  // Tinv rows (role-parity masks)
    uint8_t  uidx[NW];   // gate matrix index: (L&1)*NW + w
};
struct AllTabs {
    LayerTab lay[NLAYERS];
    uint16_t zu[NW];     // final Tinv rows -> measurement sign masks
};

__host__ __device__ constexpr unsigned swz(unsigned j) {
    return j ^ (j >> 4) ^ (j >> 9);
}

__host__ __device__ constexpr AllTabs build_all() {
    AllTabs t{};
    uint16_t Tcol[NW]  = {};
    uint16_t TiRow[NW] = {};
    for (int i = 0; i < NW; i++) { Tcol[i] = (uint16_t)(1u << i); TiRow[i] = (uint16_t)(1u << i); }

    for (int L = 0; L < NLAYERS; L++) {
        LayerTab& lt = t.lay[L];
        for (int w = 0; w < NW; w++) {
            lt.v[w]     = Tcol[w];
            lt.umask[w] = TiRow[w];
            lt.uidx[w]  = (uint8_t)((L & 1) * NW + w);
        }
        // CNOT ring layer, range r = (L%2)+1:  T' = T*Q,  Tinv' = Qinv*Tinv
        int r = (L & 1) + 1;
        uint16_t Qrow[NW]  = {};
        uint16_t QiRow[NW] = {};
        for (int i = 0; i < NW; i++) { Qrow[i] = (uint16_t)(1u << i); QiRow[i] = (uint16_t)(1u << i); }
        for (int w = NW - 1; w >= 0; w--) Qrow[(w + r) % NW]  = (uint16_t)(Qrow[(w + r) % NW]  ^ Qrow[w]);
        for (int w = 0; w < NW; w++)      QiRow[(w + r) % NW] = (uint16_t)(QiRow[(w + r) % NW] ^ QiRow[w]);
        uint16_t nT[NW]  = {};
        uint16_t nTi[NW] = {};
        for (int w = 0; w < NW; w++) {
            uint16_t c = 0;
            for (int i = 0; i < NW; i++) if ((Qrow[i] >> w) & 1) c = (uint16_t)(c ^ Tcol[i]);
            nT[w] = c;
        }
        for (int i = 0; i < NW; i++) {
            uint16_t rr = 0;
            for (int k = 0; k < NW; k++) if ((QiRow[i] >> k) & 1) rr = (uint16_t)(rr ^ TiRow[k]);
            nTi[i] = rr;
        }
        for (int i = 0; i < NW; i++) { Tcol[i] = nT[i]; TiRow[i] = nTi[i]; }
    }
    for (int i = 0; i < NW; i++) t.zu[i] = TiRow[i];
    return t;
}

// Candidate vectors for the complement-basis greedy: 14 units + 91 pairs.
__host__ __device__ constexpr uint16_t cand_vec(int idx) {
    if (idx < 14) return (uint16_t)(1u << idx);
    int k = idx - 14;
    for (int a = 0; a < 14; a++) {
        int cnt = 13 - a;
        if (k < cnt) return (uint16_t)((1u << a) | (1u << (a + 1 + k)));
        k -= cnt;
    }
    return 1;
}
#define NCAND (14 + 91)

struct SweepTab {
    uint16_t offs[32];   // pre-swizzled xor-offsets of coset members
    uint16_t umask[5];   // role-parity masks
    uint8_t  uidx[5];    // gate matrix indices
    uint16_t w[10];      // complement basis; w[i] multiplies bit i of c
};

__host__ __device__ constexpr SweepTab make_sweep(int L, int g) {
    AllTabs t = build_all();
    const int GS[3] = {5, 5, 4};
    const int W0[3] = {0, 5, 10};
    const int G = GS[g], w0 = W0[g];
    SweepTab s{};
    for (int i = 0; i < G; i++) { s.umask[i] = t.lay[L].umask[w0 + i]; s.uidx[i] = t.lay[L].uidx[w0 + i]; }
    for (int i = G; i < 5; i++) { s.umask[i] = 0; s.uidx[i] = 0; }
    for (int m = 0; m < (1 << G); m++) {
        uint16_t x = 0;
        for (int i = 0; i < G; i++) if ((m >> i) & 1) x = (uint16_t)(x ^ t.lay[L].v[w0 + i]);
        s.offs[m] = (uint16_t)swz(x);
    }
    for (int m = (1 << G); m < 32; m++) s.offs[m] = 0;

    // Row-echelon span tracker, seeded with the gate span V.
    uint16_t ech[14] = {};
    for (int i = 0; i < G; i++) {
        uint16_t x = t.lay[L].v[w0 + i];
        for (int b = 13; b >= 0; b--) if (((x >> b) & 1) && ech[b]) x = (uint16_t)(x ^ ech[b]);
        if (x) { int b = 13; while (!((x >> b) & 1)) b--; ech[b] = x; }
    }
    uint16_t bech[4] = {};       // bank-pair image echelon (4-bit)
    const int need = 14 - G;
    for (int i = 0; i < need; i++) {
        uint16_t pick = 0; bool found = false; bool bankok = false;
        for (int ci = 0; ci < NCAND && !found; ci++) {   // pass 1: span + bank rank
            uint16_t x0 = cand_vec(ci), x = x0;
            for (int b = 13; b >= 0; b--) if (((x >> b) & 1) && ech[b]) x = (uint16_t)(x ^ ech[b]);
            if (!x) continue;
            if (i < 4) {
                uint16_t im = (uint16_t)(swz(x0) & 15u);
                for (int b = 3; b >= 0; b--) if (((im >> b) & 1) && bech[b]) im = (uint16_t)(im ^ bech[b]);
                if (!im) continue;
            }
            pick = x0; found = true; bankok = true;
        }
        for (int ci = 0; ci < NCAND && !found; ci++) {   // pass 2: span only (perf fallback)
            uint16_t x0 = cand_vec(ci), x = x0;
            for (int b = 13; b >= 0; b--) if (((x >> b) & 1) && ech[b]) x = (uint16_t)(x ^ ech[b]);
            if (!x) continue;
            pick = x0; found = true; bankok = false;
        }
        {   // insert into span echelon (independence -> correctness)
            uint16_t x = pick;
            for (int b = 13; b >= 0; b--) if (((x >> b) & 1) && ech[b]) x = (uint16_t)(x ^ ech[b]);
            if (x) { int b = 13; while (!((x >> b) & 1)) b--; ech[b] = x; }
        }
        if (i < 4 && bankok) {
            uint16_t im = (uint16_t)(swz(pick) & 15u);
            for (int b = 3; b >= 0; b--) if (((im >> b) & 1) && bech[b]) im = (uint16_t)(im ^ bech[b]);
            if (im) { int b = 3; while (!((im >> b) & 1)) b--; bech[b] = im; }
        }
        s.w[i] = pick;
    }
    for (int i = need; i < 10; i++) s.w[i] = 0;
    return s;
}

// ---------------------------------------------------------------------------
// Packed f32x2 complex helpers. Amplitude packed as u64: lo=re, hi=im.
// ---------------------------------------------------------------------------
typedef unsigned long long u64;

__device__ __forceinline__ u64 pk(float lo, float hi) {
    u64 r; asm("mov.b64 %0, {%1,%2};" : "=l"(r) : "f"(lo), "f"(hi)); return r;
}
__device__ __forceinline__ u64 sw64(u64 a) {
    unsigned lo, hi;
    asm("mov.b64 {%0,%1}, %2;" : "=r"(lo), "=r"(hi) : "l"(a));
    u64 r; asm("mov.b64 %0, {%1,%2};" : "=l"(r) : "r"(hi), "r"(lo)); return r;
}
__device__ __forceinline__ u64 fma2_(u64 a, u64 b, u64 c) {
    u64 d; asm("fma.rn.f32x2 %0, %1, %2, %3;" : "=l"(d) : "l"(a), "l"(b), "l"(c)); return d;
}
__device__ __forceinline__ u64 mul2_(u64 a, u64 b) {
    u64 d; asm("mul.rn.f32x2 %0, %1, %2;" : "=l"(d) : "l"(a), "l"(b)); return d;
}

#define SGNC 0x8000000080000000ULL
#define ONEC 0x000000003F800000ULL   // pk(1.0f, 0.0f)

// ---------------------------------------------------------------------------
// Fused multi-gate sweep.  INIT=true: registers start as the basis-state
// delta (no SMEM load, no zero-init pass needed).
// ---------------------------------------------------------------------------
template <int L, int g, int G, bool INIT>
__device__ __forceinline__ void sweep(u64* __restrict__ st,
                                      const u64* __restrict__ Us,
                                      unsigned sj0) {
    constexpr SweepTab tb = make_sweep(L, g);
    constexpr int NB = 14 - G;
    constexpr int NITER = (NSTATE >> G) / NTHREADS;

#pragma unroll
    for (int kk = 0; kk < NITER; kk++) {
        unsigned c = threadIdx.x + kk * NTHREADS;
        unsigned rep = 0;
#pragma unroll
        for (int i = 0; i < NB; i++)
            rep ^= (c & (1u << i)) ? (unsigned)tb.w[i] : 0u;
        unsigned sj = swz(rep);
        u64 a[1 << G];
        if (INIT) {
#pragma unroll
            for (int m = 0; m < (1 << G); m++)
                a[m] = ((sj ^ (unsigned)tb.offs[m]) == sj0) ? ONEC : 0ULL;
        } else {
#pragma unroll
            for (int m = 0; m < (1 << G); m++) a[m] = st[sj ^ (unsigned)tb.offs[m]];
        }
#pragma unroll
        for (int i = 0; i < G; i++) {
            const u64* Ub = Us + (int)tb.uidx[i] * 4;    // broadcast LDS
            u64 bb   = (u64)(__popc(rep & (unsigned)tb.umask[i]) & 1u);
            u64 mask = (0ULL - bb) & SGNC;
            u64 A  = Ub[0];
            u64 B  = Ub[1] ^ mask;                       // w00_pm
            u64 Bn = B ^ SGNC;                           // w11_pm
            u64 C  = Ub[2] ^ mask;                       // w01_rr
            u64 Cn = C ^ SGNC;                           // w10_rr
            u64 D  = Ub[3];                              // w01_pm == w10_pm
#pragma unroll
            for (int m = 0; m < (1 << G); m++) {
                if (m & (1 << i)) continue;
                u64 a0 = a[m], a1 = a[m | (1 << i)];
                u64 a0s = sw64(a0), a1s = sw64(a1);
                a[m]            = fma2_(A, a0, fma2_(B,  a0s, fma2_(C,  a1, mul2_(D, a1s))));
                a[m | (1 << i)] = fma2_(A, a1, fma2_(Bn, a1s, fma2_(Cn, a0, mul2_(D, a0s))));
            }
        }
#pragma unroll
        for (int m = 0; m < (1 << G); m++) st[sj ^ (unsigned)tb.offs[m]] = a[m];
    }
}

template <int L>
__device__ __forceinline__ void layer(u64* __restrict__ st, const u64* __restrict__ Us) {
    sweep<L, 0, 5, false>(st, Us, 0u); __syncthreads();
    sweep<L, 1, 5, false>(st, Us, 0u); __syncthreads();
    sweep<L, 2, 4, false>(st, Us, 0u); __syncthreads();
}

__global__ void __launch_bounds__(NTHREADS, 1)
qsim_kernel(const float* __restrict__ state_batch,
            const float* __restrict__ params,
            const float* __restrict__ head_w,
            const float* __restrict__ head_b,
            float* __restrict__ out) {
    extern __shared__ u64 st[];                    // 16384 x 8B = 128 KB
    __shared__ u64   Usm[2 * NW * 4];              // 28 gates x {u_rr,u_pm,v_rr,v_pm}
    __shared__ float redsm[NWARPS * NW];

    const int b   = blockIdx.x;
    const int tid = threadIdx.x;

    // 28 distinct Rot matrices (weights shared across the 3 blocks).
    // Rot = [[u, v], [-conj(v), conj(u)]]: u = e^{-i(phi+om)/2} cos(th/2),
    // v = -e^{+i(phi-om)/2} sin(th/2).
    if (tid < 2 * NW) {
        const float* p = params + (size_t)b * NPARAMS + tid * 3;
        float phi = p[0], th = p[1], om = p[2];
        float s, c;  sincosf(0.5f * th, &s, &c);
        float sa, ca; sincosf(0.5f * (phi + om), &sa, &ca);
        float sb, cb; sincosf(0.5f * (phi - om), &sb, &cb);
        float ur =  ca * c, ui = -sa * c;
        float vr = -cb * s, vi = -sb * s;
        u64* U = &Usm[tid * 4];
        U[0] = pk( ur, ur);     // u_rr
        U[1] = pk(-ui, ui);     // u_pm
        U[2] = pk( vr, vr);     // v_rr
        U[3] = pk(-vi, vi);     // v_pm
    }

    // AngleEmbedding: RX(0 or pi) -> basis state j0 (global phase irrelevant).
    // Every thread computes j0 from 14 broadcast global loads.
    unsigned j0 = 0;
    {
        const float* sb_ = state_batch + (size_t)b * (NSTATE * 2);
#pragma unroll
        for (int w = 0; w < NW; w++) if (sb_[w] < 0.f) j0 |= (1u << w);
    }
    const unsigned sj0 = swz(j0);
    __syncthreads();                                // Usm ready

    // Layer 0: first sweep initializes state from the basis delta (no load,
    // no zero-init pass).
    sweep<0, 0, 5, true >(st, Usm, sj0); __syncthreads();
    sweep<0, 1, 5, false>(st, Usm, 0u);  __syncthreads();
    sweep<0, 2, 4, false>(st, Usm, 0u);  __syncthreads();
    layer<1>(st, Usm);
    layer<2>(st, Usm);
    layer<3>(st, Usm);
    layer<4>(st, Usm);
    layer<5>(st, Usm);

    // <Z_w> via final Tinv sign masks, then linear head
    constexpr AllTabs tt = build_all();
    float acc[NW];
#pragma unroll
    for (int w = 0; w < NW; w++) acc[w] = 0.f;
#pragma unroll
    for (int kk = 0; kk < NSTATE / NTHREADS; kk++) {
        unsigned j = (unsigned)(tid + kk * NTHREADS);
        u64 av = st[swz(j)];
        float ax = __uint_as_float((unsigned)av);
        float ay = __uint_as_float((unsigned)(av >> 32));
        float pv = ax * ax + ay * ay;
        unsigned pb = __float_as_uint(pv);
#pragma unroll
        for (int w = 0; w < NW; w++) {
            unsigned s = (__popc(j & (unsigned)tt.zu[w]) & 1u) << 31;
            acc[w] += __uint_as_float(pb ^ s);
        }
    }
#pragma unroll
    for (int w = 0; w < NW; w++) {
#pragma unroll
        for (int o = 16; o > 0; o >>= 1) acc[w] += __shfl_xor_sync(0xffffffffu, acc[w], o);
    }
    const int lane = tid & 31, warp = tid >> 5;
    if (lane == 0) {
#pragma unroll
        for (int w = 0; w < NW; w++) redsm[warp * NW + w] = acc[w];
    }
    __syncthreads();
    if (warp == 0 && lane < NW) {
        float z = 0.f;
#pragma unroll
        for (int k = 0; k < NWARPS; k++) z += redsm[k * NW + lane];
        redsm[lane] = z * head_w[lane];
    }
    __syncthreads();
    if (tid == 0) {
        float r_ = head_b[0];
#pragma unroll
        for (int w = 0; w < NW; w++) r_ += redsm[w];
        out[b] = r_;
    }
}

extern "C" void kernel_launch(void* const* d_in, const int* in_sizes, int n_in,
                              void* d_out, int out_size) {
    const float* state_batch = (const float*)d_in[0];
    const float* params      = (const float*)d_in[1];
    const float* head_w      = (const float*)d_in[2];
    const float* head_b      = (const float*)d_in[3];
    float* out = (float*)d_out;

    int B = in_sizes[0] / (NSTATE * 2);   // 512
    cudaFuncSetAttribute(qsim_kernel, cudaFuncAttributeMaxDynamicSharedMemorySize,
                         NSTATE * (int)sizeof(u64));
    qsim_kernel<<<B, NTHREADS, NSTATE * sizeof(u64)>>>(state_batch, params, head_w, head_b, out);
}

// round 11
// speedup vs baseline: 1.6036x; 1.0846x over previous
#include <cuda_runtime.h>
#include <cstdint>

#define NW 14
#define NSTATE (1 << NW)        // 16384 amplitudes
#define NLAYERS 6               // (DEPTH+1) * SEL_LAYERS
#define NTHREADS 512
#define NWARPS (NTHREADS / 32)
#define NPARAMS (2 * NW * 3)    // 84

// ---------------------------------------------------------------------------
// Compile-time GF(2) algebra: lazy CNOT permutation tracking.
// psi[x] = a[T*x]; Rot on wire w pairs (j, j^v), v = col_w(T); role parity =
// <row_w(Tinv), j>.  Storage swizzle sw(j)=j^(j>>4)^(j>>9) (linear).
// Layers grouped G=5+5+4 -> 18 sweeps.  Coset representatives from constexpr
// complement bases with GF(2)-independent bank-pair images -> 2-phase LDS/STS.
// Measurement fused into the last sweep via per-coset 4-dim Walsh-Hadamard.
// ---------------------------------------------------------------------------

struct LayerTab {
    uint16_t v[NW];      // T columns for this layer
    uint16_t umask[NW];  // Tinv rows (role-parity masks)
    uint8_t  uidx[NW];   // gate matrix index: (L&1)*NW + w
};
struct AllTabs {
    LayerTab lay[NLAYERS];
    uint16_t zu[NW];     // final Tinv rows -> measurement sign masks
};

__host__ __device__ constexpr unsigned swz(unsigned j) {
    return j ^ (j >> 4) ^ (j >> 9);
}

__host__ __device__ constexpr AllTabs build_all() {
    AllTabs t{};
    uint16_t Tcol[NW]  = {};
    uint16_t TiRow[NW] = {};
    for (int i = 0; i < NW; i++) { Tcol[i] = (uint16_t)(1u << i); TiRow[i] = (uint16_t)(1u << i); }

    for (int L = 0; L < NLAYERS; L++) {
        LayerTab& lt = t.lay[L];
        for (int w = 0; w < NW; w++) {
            lt.v[w]     = Tcol[w];
            lt.umask[w] = TiRow[w];
            lt.uidx[w]  = (uint8_t)((L & 1) * NW + w);
        }
        // CNOT ring layer, range r = (L%2)+1:  T' = T*Q,  Tinv' = Qinv*Tinv
        int r = (L & 1) + 1;
        uint16_t Qrow[NW]  = {};
        uint16_t QiRow[NW] = {};
        for (int i = 0; i < NW; i++) { Qrow[i] = (uint16_t)(1u << i); QiRow[i] = (uint16_t)(1u << i); }
        for (int w = NW - 1; w >= 0; w--) Qrow[(w + r) % NW]  = (uint16_t)(Qrow[(w + r) % NW]  ^ Qrow[w]);
        for (int w = 0; w < NW; w++)      QiRow[(w + r) % NW] = (uint16_t)(QiRow[(w + r) % NW] ^ QiRow[w]);
        uint16_t nT[NW]  = {};
        uint16_t nTi[NW] = {};
        for (int w = 0; w < NW; w++) {
            uint16_t c = 0;
            for (int i = 0; i < NW; i++) if ((Qrow[i] >> w) & 1) c = (uint16_t)(c ^ Tcol[i]);
            nT[w] = c;
        }
        for (int i = 0; i < NW; i++) {
            uint16_t rr = 0;
            for (int k = 0; k < NW; k++) if ((QiRow[i] >> k) & 1) rr = (uint16_t)(rr ^ TiRow[k]);
            nTi[i] = rr;
        }
        for (int i = 0; i < NW; i++) { Tcol[i] = nT[i]; TiRow[i] = nTi[i]; }
    }
    for (int i = 0; i < NW; i++) t.zu[i] = TiRow[i];
    return t;
}

// Candidate vectors for the complement-basis greedy: 14 units + 91 pairs.
__host__ __device__ constexpr uint16_t cand_vec(int idx) {
    if (idx < 14) return (uint16_t)(1u << idx);
    int k = idx - 14;
    for (int a = 0; a < 14; a++) {
        int cnt = 13 - a;
        if (k < cnt) return (uint16_t)((1u << a) | (1u << (a + 1 + k)));
        k -= cnt;
    }
    return 1;
}
#define NCAND (14 + 91)

struct SweepTab {
    uint16_t offs[32];   // pre-swizzled xor-offsets of coset members
    uint16_t umask[5];   // role-parity masks
    uint8_t  uidx[5];    // gate matrix indices
    uint16_t w[10];      // complement basis; w[i] multiplies bit i of c
};

__host__ __device__ constexpr SweepTab make_sweep(int L, int g) {
    AllTabs t = build_all();
    const int GS[3] = {5, 5, 4};
    const int W0[3] = {0, 5, 10};
    const int G = GS[g], w0 = W0[g];
    SweepTab s{};
    for (int i = 0; i < G; i++) { s.umask[i] = t.lay[L].umask[w0 + i]; s.uidx[i] = t.lay[L].uidx[w0 + i]; }
    for (int i = G; i < 5; i++) { s.umask[i] = 0; s.uidx[i] = 0; }
    for (int m = 0; m < (1 << G); m++) {
        uint16_t x = 0;
        for (int i = 0; i < G; i++) if ((m >> i) & 1) x = (uint16_t)(x ^ t.lay[L].v[w0 + i]);
        s.offs[m] = (uint16_t)swz(x);
    }
    for (int m = (1 << G); m < 32; m++) s.offs[m] = 0;

    // Row-echelon span tracker, seeded with the gate span V.
    uint16_t ech[14] = {};
    for (int i = 0; i < G; i++) {
        uint16_t x = t.lay[L].v[w0 + i];
        for (int b = 13; b >= 0; b--) if (((x >> b) & 1) && ech[b]) x = (uint16_t)(x ^ ech[b]);
        if (x) { int b = 13; while (!((x >> b) & 1)) b--; ech[b] = x; }
    }
    uint16_t bech[4] = {};       // bank-pair image echelon (4-bit)
    const int need = 14 - G;
    for (int i = 0; i < need; i++) {
        uint16_t pick = 0; bool found = false; bool bankok = false;
        for (int ci = 0; ci < NCAND && !found; ci++) {   // pass 1: span + bank rank
            uint16_t x0 = cand_vec(ci), x = x0;
            for (int b = 13; b >= 0; b--) if (((x >> b) & 1) && ech[b]) x = (uint16_t)(x ^ ech[b]);
            if (!x) continue;
            if (i < 4) {
                uint16_t im = (uint16_t)(swz(x0) & 15u);
                for (int b = 3; b >= 0; b--) if (((im >> b) & 1) && bech[b]) im = (uint16_t)(im ^ bech[b]);
                if (!im) continue;
            }
            pick = x0; found = true; bankok = true;
        }
        for (int ci = 0; ci < NCAND && !found; ci++) {   // pass 2: span only (perf fallback)
            uint16_t x0 = cand_vec(ci), x = x0;
            for (int b = 13; b >= 0; b--) if (((x >> b) & 1) && ech[b]) x = (uint16_t)(x ^ ech[b]);
            if (!x) continue;
            pick = x0; found = true; bankok = false;
        }
        {   // insert into span echelon (independence -> correctness)
            uint16_t x = pick;
            for (int b = 13; b >= 0; b--) if (((x >> b) & 1) && ech[b]) x = (uint16_t)(x ^ ech[b]);
            if (x) { int b = 13; while (!((x >> b) & 1)) b--; ech[b] = x; }
        }
        if (i < 4 && bankok) {
            uint16_t im = (uint16_t)(swz(pick) & 15u);
            for (int b = 3; b >= 0; b--) if (((im >> b) & 1) && bech[b]) im = (uint16_t)(im ^ bech[b]);
            if (im) { int b = 3; while (!((im >> b) & 1)) b--; bech[b] = im; }
        }
        s.w[i] = pick;
    }
    for (int i = need; i < 10; i++) s.w[i] = 0;
    return s;
}

// Measurement tables for the fused final sweep (layer 5, group 2, wires 10-13):
// twalsh[w] = 4-bit Walsh index: bit i = popc(v5[10+i] & zu[w]) & 1.
struct MeasTab {
    uint8_t  twalsh[NW];
    uint16_t zu[NW];
};
__host__ __device__ constexpr MeasTab make_meas() {
    AllTabs t = build_all();
    MeasTab m{};
    for (int w = 0; w < NW; w++) {
        m.zu[w] = t.zu[w];
        unsigned k = 0;
        for (int i = 0; i < 4; i++) {
            unsigned p = (unsigned)(t.lay[5].v[10 + i] & t.zu[w]);
            int pc = 0;
            for (int b = 0; b < 16; b++) pc += (p >> b) & 1;
            k |= (unsigned)(pc & 1) << i;
        }
        m.twalsh[w] = (uint8_t)k;
    }
    return m;
}

// ---------------------------------------------------------------------------
// Packed f32x2 complex helpers. Amplitude packed as u64: lo=re, hi=im.
// ---------------------------------------------------------------------------
typedef unsigned long long u64;

__device__ __forceinline__ u64 pk(float lo, float hi) {
    u64 r; asm("mov.b64 %0, {%1,%2};" : "=l"(r) : "f"(lo), "f"(hi)); return r;
}
__device__ __forceinline__ u64 sw64(u64 a) {
    unsigned lo, hi;
    asm("mov.b64 {%0,%1}, %2;" : "=r"(lo), "=r"(hi) : "l"(a));
    u64 r; asm("mov.b64 %0, {%1,%2};" : "=l"(r) : "r"(hi), "r"(lo)); return r;
}
__device__ __forceinline__ u64 fma2_(u64 a, u64 b, u64 c) {
    u64 d; asm("fma.rn.f32x2 %0, %1, %2, %3;" : "=l"(d) : "l"(a), "l"(b), "l"(c)); return d;
}
__device__ __forceinline__ u64 mul2_(u64 a, u64 b) {
    u64 d; asm("mul.rn.f32x2 %0, %1, %2;" : "=l"(d) : "l"(a), "l"(b)); return d;
}

#define SGNC 0x8000000080000000ULL
#define ONEC 0x000000003F800000ULL   // pk(1.0f, 0.0f)

// Apply the G gates of sweep (L,g) to NITER register cosets (stage-interleaved
// for cross-coset ILP).
template <int L, int g, int G, int NITER>
__device__ __forceinline__ void apply_gates(u64 a[NITER][1 << G],
                                            const unsigned* rep,
                                            const u64* __restrict__ Us) {
    constexpr SweepTab tb = make_sweep(L, g);
#pragma unroll
    for (int i = 0; i < G; i++) {
        const u64* Ub = Us + (int)tb.uidx[i] * 4;        // broadcast LDS
        u64 u0 = Ub[0], u1 = Ub[1], u2 = Ub[2], u3 = Ub[3];
#pragma unroll
        for (int kk = 0; kk < NITER; kk++) {
            u64 bb   = (u64)(__popc(rep[kk] & (unsigned)tb.umask[i]) & 1u);
            u64 mask = (0ULL - bb) & SGNC;
            u64 A  = u0;
            u64 B  = u1 ^ mask;                          // w00_pm
            u64 Bn = B ^ SGNC;                           // w11_pm
            u64 C  = u2 ^ mask;                          // w01_rr
            u64 Cn = C ^ SGNC;                           // w10_rr
            u64 D  = u3;                                 // w01_pm == w10_pm
#pragma unroll
            for (int m = 0; m < (1 << G); m++) {
                if (m & (1 << i)) continue;
                u64 a0 = a[kk][m], a1 = a[kk][m | (1 << i)];
                u64 a0s = sw64(a0), a1s = sw64(a1);
                a[kk][m]            = fma2_(A, a0, fma2_(B,  a0s, fma2_(C,  a1, mul2_(D, a1s))));
                a[kk][m | (1 << i)] = fma2_(A, a1, fma2_(Bn, a1s, fma2_(Cn, a0, mul2_(D, a0s))));
            }
        }
    }
}

// Generic sweep: load all cosets, compute all, store all (explicit pipeline).
template <int L, int g, int G, bool INIT>
__device__ __forceinline__ void sweep(u64* __restrict__ st,
                                      const u64* __restrict__ Us,
                                      unsigned sj0) {
    constexpr SweepTab tb = make_sweep(L, g);
    constexpr int NB = 14 - G;
    constexpr int NITER = (NSTATE >> G) / NTHREADS;

    unsigned rep[NITER], sj[NITER];
    u64 a[NITER][1 << G];
#pragma unroll
    for (int kk = 0; kk < NITER; kk++) {
        unsigned c = threadIdx.x + kk * NTHREADS;
        unsigned r = 0;
#pragma unroll
        for (int i = 0; i < NB; i++)
            r ^= (c & (1u << i)) ? (unsigned)tb.w[i] : 0u;
        rep[kk] = r; sj[kk] = swz(r);
        if (INIT) {
#pragma unroll
            for (int m = 0; m < (1 << G); m++)
                a[kk][m] = ((sj[kk] ^ (unsigned)tb.offs[m]) == sj0) ? ONEC : 0ULL;
        } else {
#pragma unroll
            for (int m = 0; m < (1 << G); m++) a[kk][m] = st[sj[kk] ^ (unsigned)tb.offs[m]];
        }
    }
    apply_gates<L, g, G, NITER>(a, rep, Us);
#pragma unroll
    for (int kk = 0; kk < NITER; kk++)
#pragma unroll
        for (int m = 0; m < (1 << G); m++) st[sj[kk] ^ (unsigned)tb.offs[m]] = a[kk][m];
}

// Final sweep (layer 5, group 2): apply gates, then fold the |psi|^2
// measurement in registers (4-dim Walsh-Hadamard per coset). No stores.
__device__ __forceinline__ void sweep_final(const u64* __restrict__ st,
                                            const u64* __restrict__ Us,
                                            float* __restrict__ acc) {
    constexpr SweepTab tb = make_sweep(5, 2);
    constexpr MeasTab  mt = make_meas();
    constexpr int G = 4, NB = 10, NITER = 2;

    unsigned rep[NITER], sj[NITER];
    u64 a[NITER][16];
#pragma unroll
    for (int kk = 0; kk < NITER; kk++) {
        unsigned c = threadIdx.x + kk * NTHREADS;
        unsigned r = 0;
#pragma unroll
        for (int i = 0; i < NB; i++)
            r ^= (c & (1u << i)) ? (unsigned)tb.w[i] : 0u;
        rep[kk] = r; sj[kk] = swz(r);
#pragma unroll
        for (int m = 0; m < 16; m++) a[kk][m] = st[sj[kk] ^ (unsigned)tb.offs[m]];
    }
    apply_gates<5, 2, G, NITER>(a, rep, Us);

#pragma unroll
    for (int kk = 0; kk < NITER; kk++) {
        float pv[16];
#pragma unroll
        for (int m = 0; m < 16; m++) {
            float ax = __uint_as_float((unsigned)a[kk][m]);
            float ay = __uint_as_float((unsigned)(a[kk][m] >> 32));
            pv[m] = ax * ax + ay * ay;
        }
        // 4-stage Walsh-Hadamard: pv[k] = sum_m (-1)^{popc(k&m)} |a_m|^2
#pragma unroll
        for (int i = 0; i < 4; i++) {
#pragma unroll
            for (int m = 0; m < 16; m++) {
                if (m & (1 << i)) continue;
                float x = pv[m], y = pv[m | (1 << i)];
                pv[m] = x + y; pv[m | (1 << i)] = x - y;
            }
        }
#pragma unroll
        for (int w = 0; w < NW; w++) {
            unsigned bs = (__popc(rep[kk] & (unsigned)mt.zu[w]) & 1u) << 31;
            acc[w] += __uint_as_float(__float_as_uint(pv[mt.twalsh[w]]) ^ bs);
        }
    }
}

template <int L>
__device__ __forceinline__ void layer(u64* __restrict__ st, const u64* __restrict__ Us) {
    sweep<L, 0, 5, false>(st, Us, 0u); __syncthreads();
    sweep<L, 1, 5, false>(st, Us, 0u); __syncthreads();
    sweep<L, 2, 4, false>(st, Us, 0u); __syncthreads();
}

__global__ void __launch_bounds__(NTHREADS, 1)
qsim_kernel(const float* __restrict__ state_batch,
            const float* __restrict__ params,
            const float* __restrict__ head_w,
            const float* __restrict__ head_b,
            float* __restrict__ out) {
    extern __shared__ u64 st[];                    // 16384 x 8B = 128 KB
    __shared__ u64   Usm[2 * NW * 4];              // 28 gates x {u_rr,u_pm,v_rr,v_pm}
    __shared__ float redsm[NWARPS * NW];

    const int b   = blockIdx.x;
    const int tid = threadIdx.x;

    // 28 distinct Rot matrices (weights shared across the 3 blocks).
    // Rot = [[u, v], [-conj(v), conj(u)]]: u = e^{-i(phi+om)/2} cos(th/2),
    // v = -e^{+i(phi-om)/2} sin(th/2).
    if (tid < 2 * NW) {
        const float* p = params + (size_t)b * NPARAMS + tid * 3;
        float phi = p[0], th = p[1], om = p[2];
        float s, c;  sincosf(0.5f * th, &s, &c);
        float sa, ca; sincosf(0.5f * (phi + om), &sa, &ca);
        float sb, cb; sincosf(0.5f * (phi - om), &sb, &cb);
        float ur =  ca * c, ui = -sa * c;
        float vr = -cb * s, vi = -sb * s;
        u64* U = &Usm[tid * 4];
        U[0] = pk( ur, ur);     // u_rr
        U[1] = pk(-ui, ui);     // u_pm
        U[2] = pk( vr, vr);     // v_rr
        U[3] = pk(-vi, vi);     // v_pm
    }

    // AngleEmbedding: RX(0 or pi) -> basis state j0 (global phase irrelevant).
    unsigned j0 = 0;
    {
        const float* sb_ = state_batch + (size_t)b * (NSTATE * 2);
#pragma unroll
        for (int w = 0; w < NW; w++) if (sb_[w] < 0.f) j0 |= (1u << w);
    }
    const unsigned sj0 = swz(j0);
    __syncthreads();                                // Usm ready

    // Layer 0: first sweep initializes from the basis delta (no load/zero pass)
    sweep<0, 0, 5, true >(st, Usm, sj0); __syncthreads();
    sweep<0, 1, 5, false>(st, Usm, 0u);  __syncthreads();
    sweep<0, 2, 4, false>(st, Usm, 0u);  __syncthreads();
    layer<1>(st, Usm);
    layer<2>(st, Usm);
    layer<3>(st, Usm);
    layer<4>(st, Usm);
    // Layer 5: groups 0,1 normal; group 2 fused with measurement (no stores,
    // no separate measurement pass).
    sweep<5, 0, 5, false>(st, Usm, 0u); __syncthreads();
    sweep<5, 1, 5, false>(st, Usm, 0u); __syncthreads();

    float acc[NW];
#pragma unroll
    for (int w = 0; w < NW; w++) acc[w] = 0.f;
    sweep_final(st, Usm, acc);

    // Block-reduce acc and apply linear head
#pragma unroll
    for (int w = 0; w < NW; w++) {
#pragma unroll
        for (int o = 16; o > 0; o >>= 1) acc[w] += __shfl_xor_sync(0xffffffffu, acc[w], o);
    }
    const int lane = tid & 31, warp = tid >> 5;
    if (lane == 0) {
#pragma unroll
        for (int w = 0; w < NW; w++) redsm[warp * NW + w] = acc[w];
    }
    __syncthreads();
    if (warp == 0 && lane < NW) {
        float z = 0.f;
#pragma unroll
        for (int k = 0; k < NWARPS; k++) z += redsm[k * NW + lane];
        redsm[lane] = z * head_w[lane];
    }
    __syncthreads();
    if (tid == 0) {
        float r_ = head_b[0];
#pragma unroll
        for (int w = 0; w < NW; w++) r_ += redsm[w];
        out[b] = r_;
    }
}

extern "C" void kernel_launch(void* const* d_in, const int* in_sizes, int n_in,
                              void* d_out, int out_size) {
    const float* state_batch = (const float*)d_in[0];
    const float* params      = (const float*)d_in[1];
    const float* head_w      = (const float*)d_in[2];
    const float* head_b      = (const float*)d_in[3];
    float* out = (float*)d_out;

    int B = in_sizes[0] / (NSTATE * 2);   // 512
    cudaFuncSetAttribute(qsim_kernel, cudaFuncAttributeMaxDynamicSharedMemorySize,
                         NSTATE * (int)sizeof(u64));
    qsim_kernel<<<B, NTHREADS, NSTATE * sizeof(u64)>>>(state_batch, params, head_w, head_b, out);
}